// round 6
// baseline (speedup 1.0000x reference)
#include <cuda_runtime.h>
#include <cuda_fp16.h>
#include <cstdint>

// Sparse embedding-bag: out[b,:] = bias + sum_k weight[ft_ics[b,k],:] * ft_vals[b,k]
// B=16384, K=32, N_OUT=256. Table 41024x256 fp32 = 42 MB.
//
// R6: fp16 table pre-pass (R5 win) + issue-stream slimming in the gather:
//   - fma.rn.f32x2 (FFMA2): 2 FMAs/issue
//   - idx+val fused into one LDS.64 broadcast (uint2)
//   - b64 packed accumulators + st.global.cs.b64 outputs
// ~600 -> ~420 issue slots/thread; 6 blocks/SM for latency cover.

#define N_IN_ROWS 41024
#define N_OUT_COLS 256
#define K_FEATS 32
#define ROWS_PER_BLOCK 8
#define KU 4

__device__ __half g_w16[(size_t)N_IN_ROWS * N_OUT_COLS];

// ---------------- conversion: fp32 table -> fp16 table (streaming) ----------
__global__ __launch_bounds__(256)
void convert_w16_kernel(const float4* __restrict__ w32)
{
    const size_t n4 = (size_t)N_IN_ROWS * N_OUT_COLS / 4;
    uint2* dst = reinterpret_cast<uint2*>(g_w16);
    for (size_t i = (size_t)blockIdx.x * blockDim.x + threadIdx.x;
         i < n4; i += (size_t)gridDim.x * blockDim.x) {
        const float4 w = __ldg(&w32[i]);
        __half2 h0 = __floats2half2_rn(w.x, w.y);
        __half2 h1 = __floats2half2_rn(w.z, w.w);
        uint2 u;
        u.x = *reinterpret_cast<unsigned*>(&h0);
        u.y = *reinterpret_cast<unsigned*>(&h1);
        dst[i] = u;
    }
}

// cvt half2 -> packed f32x2, then packed FFMA2 into a b64 accumulator.
__device__ __forceinline__ void fma2_h2(unsigned long long& acc, unsigned h2,
                                        unsigned long long vv)
{
    asm("{\n\t"
        ".reg .b16 hl, hh;\n\t"
        ".reg .f32 lo, hi;\n\t"
        ".reg .b64 w2;\n\t"
        "mov.b32 {hl, hh}, %1;\n\t"
        "cvt.f32.f16 lo, hl;\n\t"
        "cvt.f32.f16 hi, hh;\n\t"
        "mov.b64 w2, {lo, hi};\n\t"
        "fma.rn.f32x2 %0, %2, w2, %0;\n\t"
        "}"
        : "+l"(acc) : "r"(h2), "l"(vv));
}

// ---------------- gather: fp16 table, packed fp32 accumulate ----------------
// Warp = one batch row. Lane tx owns column pairs {c*64+2tx, +1 : c=0..3}.
// 4 coalesced LDG.32 per feature (one 128B line each), KU=4 front-batched.
__global__ __launch_bounds__(32 * ROWS_PER_BLOCK, 6)
void ft_embed_bag_kernel(const int* __restrict__ ics,
                         const float* __restrict__ vals,
                         const float* __restrict__ bias,   // [256]
                         float* __restrict__ out)          // [B][256]
{
    __shared__ uint2 s_iv[ROWS_PER_BLOCK][K_FEATS];  // .x = idx, .y = val bits

    const int ty = threadIdx.y;
    const int tx = threadIdx.x;
    const int b  = blockIdx.x * ROWS_PER_BLOCK + ty;

    {
        const int   raw = __ldg(&ics[b * K_FEATS + tx]);
        const float v   = __ldg(&vals[b * K_FEATS + tx]);
        const bool valid = (raw >= 0);
        uint2 iv;
        iv.x = valid ? (unsigned)raw : 0u;
        iv.y = valid ? __float_as_uint(v) : 0u;
        s_iv[ty][tx] = iv;
    }
    __syncwarp();

    // Packed accumulators: acc2[c] holds output cols (c*64+2tx, c*64+2tx+1).
    unsigned long long acc2[4];
    const float2* b2 = reinterpret_cast<const float2*>(bias);
    #pragma unroll
    for (int c = 0; c < 4; ++c) {
        const float2 bv = __ldg(b2 + c * 32 + tx);
        asm("mov.b64 %0, {%1, %2};" : "=l"(acc2[c]) : "f"(bv.x), "f"(bv.y));
    }

    const __half2* wtab = reinterpret_cast<const __half2*>(g_w16);

    #pragma unroll
    for (int k0 = 0; k0 < K_FEATS; k0 += KU) {
        unsigned           idx[KU];
        unsigned long long vv[KU];
        #pragma unroll
        for (int j = 0; j < KU; ++j) {
            const uint2 iv = s_iv[ty][k0 + j];        // one LDS.64 broadcast
            idx[j] = iv.x;
            const float v = __uint_as_float(iv.y);
            asm("mov.b64 %0, {%1, %1};" : "=l"(vv[j]) : "f"(v));
        }

        // Front-batch 4*KU independent coalesced LDG.32 (one 128B line each).
        unsigned w[KU][4];
        #pragma unroll
        for (int j = 0; j < KU; ++j) {
            const __half2* base = wtab + (size_t)idx[j] * 128 + tx;
            #pragma unroll
            for (int c = 0; c < 4; ++c)
                w[j][c] = __ldg(reinterpret_cast<const unsigned*>(base + c * 32));
        }

        #pragma unroll
        for (int j = 0; j < KU; ++j)
            #pragma unroll
            for (int c = 0; c < 4; ++c)
                fma2_h2(acc2[c], w[j][c], vv[j]);
    }

    // Streaming 64-bit stores (single-use output), coalesced per c.
    float* orow = out + (size_t)b * N_OUT_COLS;
    #pragma unroll
    for (int c = 0; c < 4; ++c) {
        float* p = orow + c * 64 + 2 * tx;
        asm volatile("st.global.cs.b64 [%0], %1;" :: "l"(p), "l"(acc2[c]));
    }
}

extern "C" void kernel_launch(void* const* d_in, const int* in_sizes, int n_in,
                              void* d_out, int out_size)
{
    const int*   ics    = (const int*)d_in[0];
    const float* vals   = (const float*)d_in[1];
    const float* weight = (const float*)d_in[2];
    const float* bias   = (const float*)d_in[3];
    float*       out    = (float*)d_out;

    const int B = in_sizes[0] / K_FEATS;  // 16384

    convert_w16_kernel<<<2048, 256>>>((const float4*)weight);

    dim3 block(32, ROWS_PER_BLOCK);
    dim3 grid(B / ROWS_PER_BLOCK);
    ft_embed_bag_kernel<<<grid, block>>>(ics, vals, bias, out);
}